// round 13
// baseline (speedup 1.0000x reference)
#include <cuda_runtime.h>
#include <cuda_bf16.h>
#include <cuda_fp16.h>
#include <math.h>
#include <stdint.h>

#define EDIM 1024
#define NTOK 4096          // B*T
#define FDIM 4096
#define NH   16

// ---------------- scratch (__device__ globals; no allocs allowed) ----------
__device__ __nv_bfloat16 g_h  [NTOK * EDIM];            // LN out (bf16)
__device__ __half        g_qkv[NTOK * 3 * EDIM];        // fp16 (attn input)
__device__ __nv_bfloat16 g_att[NTOK * EDIM];            // attn out (bf16)
__device__ float         g_x1 [NTOK * EDIM];            // residual after attn
__device__ __nv_bfloat16 g_ff [(size_t)NTOK * FDIM];    // fc1-gelu out (bf16)
__device__ __nv_bfloat16 g_w  [12 * 1024 * 1024];       // bf16 weights
#define OFF_WQKV 0
#define OFF_WOUT (3*1024*1024)
#define OFF_WFC1 (4*1024*1024)
#define OFF_WFC2 (8*1024*1024)

__device__ __forceinline__ unsigned bfpack(float lo, float hi) {
    __nv_bfloat162 p = __floats2bfloat162_rn(lo, hi);
    return *(unsigned*)&p;
}
__device__ __forceinline__ unsigned hpack(float lo, float hi) {
    __half2 p = __floats2half2_rn(lo, hi);
    return *(unsigned*)&p;
}

// fast 2^y for softmax (y<=0): exponent bits + deg-5 poly on frac. FMA-pipe only.
// (scores are pre-scaled by log2e, so softmax is unchanged: 2^(s*log2e)=e^s)
__device__ __forceinline__ float fexp2(float y) {
    y = fmaxf(y, -80.f);
    float fl = floorf(y);
    float f = y - fl;
    float p =            1.3333558146e-3f;
    p = fmaf(p, f, 9.6181291076e-3f);
    p = fmaf(p, f, 5.5504108664e-2f);
    p = fmaf(p, f, 2.4022650696e-1f);
    p = fmaf(p, f, 6.9314718056e-1f);
    p = fmaf(p, f, 1.0f);
    int e = (int)fl;
    return p * __int_as_float((e + 127) << 23);
}

__device__ __forceinline__ void mma_bf16(float* d, const unsigned* a, const unsigned* b) {
    asm volatile(
        "mma.sync.aligned.m16n8k16.row.col.f32.bf16.bf16.f32 "
        "{%0,%1,%2,%3},{%4,%5,%6,%7},{%8,%9},{%0,%1,%2,%3};"
        : "+f"(d[0]), "+f"(d[1]), "+f"(d[2]), "+f"(d[3])
        : "r"(a[0]), "r"(a[1]), "r"(a[2]), "r"(a[3]), "r"(b[0]), "r"(b[1]));
}
__device__ __forceinline__ void mma_f16(float* d, const unsigned* a, unsigned b0, unsigned b1) {
    asm volatile(
        "mma.sync.aligned.m16n8k16.row.col.f32.f16.f16.f32 "
        "{%0,%1,%2,%3},{%4,%5,%6,%7},{%8,%9},{%0,%1,%2,%3};"
        : "+f"(d[0]), "+f"(d[1]), "+f"(d[2]), "+f"(d[3])
        : "r"(a[0]), "r"(a[1]), "r"(a[2]), "r"(a[3]), "r"(b0), "r"(b1));
}
__device__ __forceinline__ void ldsm4(unsigned& r0, unsigned& r1, unsigned& r2, unsigned& r3, uint32_t addr) {
    asm volatile("ldmatrix.sync.aligned.m8n8.x4.shared.b16 {%0,%1,%2,%3}, [%4];"
                 : "=r"(r0), "=r"(r1), "=r"(r2), "=r"(r3) : "r"(addr));
}
__device__ __forceinline__ void ldsm4t(unsigned& r0, unsigned& r1, unsigned& r2, unsigned& r3, uint32_t addr) {
    asm volatile("ldmatrix.sync.aligned.m8n8.x4.trans.shared.b16 {%0,%1,%2,%3}, [%4];"
                 : "=r"(r0), "=r"(r1), "=r"(r2), "=r"(r3) : "r"(addr));
}

__device__ __forceinline__ uint32_t smem_u32g(const void* p) {
    uint32_t a;
    asm("{ .reg .u64 t; cvta.to.shared.u64 t, %1; cvt.u32.u64 %0, t; }" : "=r"(a) : "l"(p));
    return a;
}

// ---------------- weight convert: two tensors per launch --------------------
__global__ __launch_bounds__(256) void cvt2(
    const float4* __restrict__ sA, uint2* __restrict__ dA, int nA,
    const float4* __restrict__ sB, uint2* __restrict__ dB)
{
    int bid = blockIdx.x;
    const float4* s; uint2* d; int local;
    if (bid < nA) { s = sA; d = dA; local = bid; }
    else          { s = sB; d = dB; local = bid - nA; }
    int i0 = local * 1024 + threadIdx.x;
    float4 v0 = s[i0];
    float4 v1 = s[i0 + 256];
    float4 v2 = s[i0 + 512];
    float4 v3 = s[i0 + 768];
    d[i0]       = (uint2){ bfpack(v0.x, v0.y), bfpack(v0.z, v0.w) };
    d[i0 + 256] = (uint2){ bfpack(v1.x, v1.y), bfpack(v1.z, v1.w) };
    d[i0 + 512] = (uint2){ bfpack(v2.x, v2.y), bfpack(v2.z, v2.w) };
    d[i0 + 768] = (uint2){ bfpack(v3.x, v3.y), bfpack(v3.z, v3.w) };
}

// ---------------- LayerNorm (fp32 in, bf16 out) ----------------------------
__global__ __launch_bounds__(256) void ln_kernel(
    const float* __restrict__ x, const float* __restrict__ w,
    const float* __restrict__ b, __nv_bfloat16* __restrict__ out)
{
    __shared__ float red[2][8];
    int row = blockIdx.x;
    int tid = threadIdx.x;
    const float4* xr = (const float4*)(x + (size_t)row * EDIM);
    float4 v = xr[tid];
    float s  = v.x + v.y + v.z + v.w;
    float ss = v.x*v.x + v.y*v.y + v.z*v.z + v.w*v.w;
    #pragma unroll
    for (int o = 16; o; o >>= 1) {
        s  += __shfl_xor_sync(0xffffffffu, s,  o);
        ss += __shfl_xor_sync(0xffffffffu, ss, o);
    }
    int wid = tid >> 5, lid = tid & 31;
    if (lid == 0) { red[0][wid] = s; red[1][wid] = ss; }
    __syncthreads();
    s = 0.f; ss = 0.f;
    #pragma unroll
    for (int i = 0; i < 8; i++) { s += red[0][i]; ss += red[1][i]; }
    float mu  = s * (1.0f / EDIM);
    float var = ss * (1.0f / EDIM) - mu * mu;
    float inv = rsqrtf(var + 1e-5f);
    float4 wv = ((const float4*)w)[tid];
    float4 bv = ((const float4*)b)[tid];
    float o0 = (v.x - mu) * inv * wv.x + bv.x;
    float o1 = (v.y - mu) * inv * wv.y + bv.y;
    float o2 = (v.z - mu) * inv * wv.z + bv.z;
    float o3 = (v.w - mu) * inv * wv.w + bv.w;
    uint2 o = { bfpack(o0, o1), bfpack(o2, o3) };
    ((uint2*)(out + (size_t)row * EDIM))[tid] = o;
}

// ---------------------------------------------------------------------------
// bf16 mma.sync GEMM, 2 CTAs/SM.  C[M,N] = A[M,K] @ Bw[N,K]^T.
// Tile 128x128xBK64; 8 warps as 2(m)x4(n) -> 64x32 warp tiles (acc=64 regs).
// 3-stage cp.async, early prefetch with TWO barriers per iteration:
//   sync (reads of overwrite-target done) -> load(t+2) -> commit
//   -> wait_group 2 (own tile-t copies)   -> sync (ALL tile-t copies visible)
//   -> mma(t)
// Rows 128B data + 16B pad (stride 144B) -> conflict-free ldmatrix.
// EPI: 0 = +bias -> fp32; 1 = +bias+residual -> fp32;
//      2 = +bias+GELU -> bf16; 3 = +bias -> fp16
// ---------------------------------------------------------------------------
template <int EPI>
__global__ __launch_bounds__(256, 2) void gemm_tc(
    const __nv_bfloat16* __restrict__ A, const __nv_bfloat16* __restrict__ Bw,
    const float* __restrict__ bias, const float* __restrict__ R,
    void* __restrict__ Cv, int M, int N, int K)
{
    constexpr int BM = 128, BN = 128, NST = 3;
    constexpr uint32_t ROWB  = 144;
    constexpr uint32_t AOFF  = BM * ROWB;              // 18432
    constexpr uint32_t STAGE = (BM + BN) * ROWB;       // 36864 B

    extern __shared__ char dsm[];
    uint32_t sb = smem_u32g(dsm);
    int tid = threadIdx.x, warp = tid >> 5, lane = tid & 31;
    int m0 = blockIdx.y * BM, n0 = blockIdx.x * BN;
    int wm = (warp >> 2) * 64;
    int wn = (warp & 3) * 32;
    int T = K >> 6;

    float acc[4][4][4];
    #pragma unroll
    for (int i = 0; i < 4; i++)
        #pragma unroll
        for (int j = 0; j < 4; j++)
            #pragma unroll
            for (int k = 0; k < 4; k++) acc[i][j][k] = 0.f;

    auto load_tile = [&](int t, int s) {
        int k0 = t << 6;
        uint32_t base = sb + (uint32_t)s * STAGE;
        #pragma unroll
        for (int j = 0; j < 8; j++) {
            int idx = tid + j * 256;            // 2048 16B-chunks per stage
            bool isB = idx >= 1024;
            int li = idx & 1023;
            int r  = li >> 3;
            int ch = li & 7;
            const __nv_bfloat16* g = isB ? (Bw + (size_t)(n0 + r) * K + k0 + ch * 8)
                                         : (A  + (size_t)(m0 + r) * K + k0 + ch * 8);
            uint32_t dst = base + (isB ? AOFF : 0u) + (uint32_t)r * ROWB + ch * 16;
            asm volatile("cp.async.cg.shared.global [%0], [%1], 16;" :: "r"(dst), "l"(g));
        }
    };

    load_tile(0, 0);
    asm volatile("cp.async.commit_group;" ::: "memory");
    load_tile(1, 1);
    asm volatile("cp.async.commit_group;" ::: "memory");

    uint32_t lm   = lane & 15;
    uint32_t hi16 = ((lane >> 4) & 1) * 16;
    uint32_t aoff[4], boff[2];
    #pragma unroll
    for (int mt = 0; mt < 4; mt++) aoff[mt] = (uint32_t)(wm + mt * 16 + lm) * ROWB + hi16;
    #pragma unroll
    for (int p = 0; p < 2; p++)    boff[p]  = AOFF + (uint32_t)(wn + p * 16 + lm) * ROWB + hi16;

    for (int t = 0; t < T; t++) {
        // barrier 1: all warps finished reading buffer (t+2)%NST (= tile t-1)
        __syncthreads();
        // early prefetch: issue tile t+2 BEFORE blocking on tile t
        if (t + 2 < T) load_tile(t + 2, (t + 2) % NST);
        asm volatile("cp.async.commit_group;" ::: "memory");
        // own copies of tile t complete (FIFO: <=2 pending newest)
        asm volatile("cp.async.wait_group 2;" ::: "memory");
        // barrier 2: EVERY thread's tile-t copies now visible to all
        __syncthreads();

        uint32_t base = sb + (uint32_t)(t % NST) * STAGE;

        #pragma unroll
        for (int ks = 0; ks < 4; ks++) {
            unsigned a[4][4], b[4][2];
            #pragma unroll
            for (int mt = 0; mt < 4; mt++)
                ldsm4(a[mt][0], a[mt][1], a[mt][2], a[mt][3], base + aoff[mt] + ks * 32);
            #pragma unroll
            for (int p = 0; p < 2; p++) {
                unsigned r0, r1, r2, r3;
                ldsm4(r0, r1, r2, r3, base + boff[p] + ks * 32);
                b[2*p][0] = r0; b[2*p+1][0] = r1; b[2*p][1] = r2; b[2*p+1][1] = r3;
            }
            #pragma unroll
            for (int mt = 0; mt < 4; mt++)
                #pragma unroll
                for (int nt = 0; nt < 4; nt++)
                    mma_bf16(acc[mt][nt], a[mt], b[nt]);
        }
    }

    // epilogue
    float* C = (float*)Cv;
    __nv_bfloat16* Cb = (__nv_bfloat16*)Cv;
    __half* Ch = (__half*)Cv;
    int q = lane >> 2;
    int cc = (lane & 3) * 2;
    #pragma unroll
    for (int mt = 0; mt < 4; mt++) {
        #pragma unroll
        for (int nt = 0; nt < 4; nt++) {
            int row = m0 + wm + mt * 16 + q;
            int col = n0 + wn + nt * 8 + cc;
            float bx = bias[col], by = bias[col + 1];
            float v0 = acc[mt][nt][0] + bx, v1 = acc[mt][nt][1] + by;
            float v2 = acc[mt][nt][2] + bx, v3 = acc[mt][nt][3] + by;
            if (EPI == 1) {
                float2 r0 = *(const float2*)&R[(size_t)row * N + col];
                float2 r1 = *(const float2*)&R[(size_t)(row + 8) * N + col];
                v0 += r0.x; v1 += r0.y; v2 += r1.x; v3 += r1.y;
            }
            if (EPI == 2) {
                v0 = 0.5f * v0 * (1.0f + erff(v0 * 0.70710678118f));
                v1 = 0.5f * v1 * (1.0f + erff(v1 * 0.70710678118f));
                v2 = 0.5f * v2 * (1.0f + erff(v2 * 0.70710678118f));
                v3 = 0.5f * v3 * (1.0f + erff(v3 * 0.70710678118f));
                *(unsigned*)&Cb[(size_t)row * N + col]       = bfpack(v0, v1);
                *(unsigned*)&Cb[(size_t)(row + 8) * N + col] = bfpack(v2, v3);
            } else if (EPI == 3) {
                *(unsigned*)&Ch[(size_t)row * N + col]       = hpack(v0, v1);
                *(unsigned*)&Ch[(size_t)(row + 8) * N + col] = hpack(v2, v3);
            } else {
                float2 o0 = {v0, v1}, o1 = {v2, v3};
                *(float2*)&C[(size_t)row * N + col] = o0;
                *(float2*)&C[(size_t)(row + 8) * N + col] = o1;
            }
        }
    }
}

// ---------------------------------------------------------------------------
// FA2 causal attention: 128-query CTA, 256 threads (8 warps x 16 rows).
// fp16 mma; K/V cp.async double-buffered [s][d]; V frags via ldmatrix.trans.
// Softmax in exp2 domain: Q pre-scaled by (1/8)*log2e; fexp2 has no mul.
// NOTE: K/V wait uses wait_group THEN __syncthreads (visibility order).
// ---------------------------------------------------------------------------
#define ATP 72
#define ATT_SMEM 55296
__global__ __launch_bounds__(256, 2) void attn_fa(
    const __half* __restrict__ qkv, __nv_bfloat16* __restrict__ att)
{
    extern __shared__ char asmem[];
    uint32_t sb = smem_u32g(asmem);
    uint32_t sQ = sb;
    uint32_t sKa[2] = { sb + 18432, sb + 27648 };
    uint32_t sVa[2] = { sb + 36864, sb + 46080 };

    int qt = 7 - blockIdx.x;
    int bh = blockIdx.y;
    int b = bh >> 4, h = bh & 15;
    int tid = threadIdx.x, warp = tid >> 5, lane = tid & 31;
    int g = lane >> 2, c4 = lane & 3;
    uint32_t lm = lane & 15;
    uint32_t hi16 = ((lane >> 4) & 1) * 16;

    const __half* base = qkv + (size_t)b * 1024 * 3072 + h * 64;

    auto loadQ = [&]() {
        #pragma unroll
        for (int i = 0; i < 4; i++) {
            int idx = tid + i * 256;
            int r = idx >> 3, ch = idx & 7;
            const __half* gp = base + (size_t)(qt * 128 + r) * 3072 + ch * 8;
            asm volatile("cp.async.cg.shared.global [%0], [%1], 16;"
                         :: "r"(sQ + r * (ATP * 2) + ch * 16), "l"(gp));
        }
    };
    auto loadKV = [&](int kt, int buf) {
        #pragma unroll
        for (int i = 0; i < 4; i++) {
            int idx = tid + i * 256;
            bool isV = idx >= 512;
            int li = isV ? idx - 512 : idx;
            int r = li >> 3, ch = li & 7;
            const __half* gp = base + (size_t)(kt * 64 + r) * 3072
                             + (isV ? 2048 : 1024) + ch * 8;
            uint32_t dst = (isV ? sVa[buf] : sKa[buf]) + r * (ATP * 2) + ch * 16;
            asm volatile("cp.async.cg.shared.global [%0], [%1], 16;"
                         :: "r"(dst), "l"(gp));
        }
    };

    loadQ();
    loadKV(0, 0);
    asm volatile("cp.async.commit_group;" ::: "memory");
    asm volatile("cp.async.wait_group 0;" ::: "memory");
    __syncthreads();

    // Q fragments, pre-scaled by (1/8)*log2e -> scores are log2-domain
    unsigned qa[4][4];
    {
        uint32_t qoff = sQ + (uint32_t)(warp * 16 + lm) * (ATP * 2) + hi16;
        #pragma unroll
        for (int s = 0; s < 4; s++)
            ldsm4(qa[s][0], qa[s][1], qa[s][2], qa[s][3], qoff + s * 32);
        __half2 sc = __float2half2_rn(0.18033688f);   // 0.125 * log2(e)
        #pragma unroll
        for (int s = 0; s < 4; s++)
            #pragma unroll
            for (int j = 0; j < 4; j++) {
                __half2 v = __hmul2(*(__half2*)&qa[s][j], sc);
                qa[s][j] = *(unsigned*)&v;
            }
    }

    int vm = lane >> 3, vr8 = lane & 7;
    uint32_t vfoff = (uint32_t)(((vm & 1) * 8 + vr8) * (ATP * 2) + (vm >> 1) * 16);

    float m0 = -1e30f, m1 = -1e30f, l0 = 0.f, l1 = 0.f;
    float o[8][4];
    #pragma unroll
    for (int j = 0; j < 8; j++)
        #pragma unroll
        for (int e = 0; e < 4; e++) o[j][e] = 0.f;

    int row0 = qt * 128 + warp * 16 + g, row1 = row0 + 8;
    int nkt = 2 * qt + 2;

    for (int kt = 0; kt < nkt; kt++) {
        int cb = kt & 1;
        bool more = kt + 1 < nkt;
        if (more) {
            loadKV(kt + 1, cb ^ 1);
            asm volatile("cp.async.commit_group;" ::: "memory");
        }

        float s[8][4];
        #pragma unroll
        for (int j = 0; j < 8; j++)
            #pragma unroll
            for (int e = 0; e < 4; e++) s[j][e] = 0.f;
        #pragma unroll
        for (int ks = 0; ks < 4; ks++) {
            #pragma unroll
            for (int p = 0; p < 4; p++) {
                unsigned r0, r1, r2, r3;
                ldsm4(r0, r1, r2, r3, sKa[cb] + (uint32_t)(p * 16 + lm) * (ATP * 2) + hi16 + ks * 32);
                mma_f16(s[2*p],   qa[ks], r0, r2);
                mma_f16(s[2*p+1], qa[ks], r1, r3);
            }
        }

        if (kt >= 2 * qt) {
            int colb = kt * 64 + c4 * 2;
            #pragma unroll
            for (int nt = 0; nt < 8; nt++) {
                int c0 = colb + nt * 8, c1 = c0 + 1;
                s[nt][0] = (c0 <= row0) ? s[nt][0] : -1e30f;
                s[nt][1] = (c1 <= row0) ? s[nt][1] : -1e30f;
                s[nt][2] = (c0 <= row1) ? s[nt][2] : -1e30f;
                s[nt][3] = (c1 <= row1) ? s[nt][3] : -1e30f;
            }
        }

        float mx0 = -1e30f, mx1 = -1e30f;
        #pragma unroll
        for (int nt = 0; nt < 8; nt++) {
            mx0 = fmaxf(mx0, fmaxf(s[nt][0], s[nt][1]));
            mx1 = fmaxf(mx1, fmaxf(s[nt][2], s[nt][3]));
        }
        mx0 = fmaxf(mx0, __shfl_xor_sync(0xffffffffu, mx0, 1));
        mx0 = fmaxf(mx0, __shfl_xor_sync(0xffffffffu, mx0, 2));
        mx1 = fmaxf(mx1, __shfl_xor_sync(0xffffffffu, mx1, 1));
        mx1 = fmaxf(mx1, __shfl_xor_sync(0xffffffffu, mx1, 2));
        float mn0 = fmaxf(m0, mx0), mn1 = fmaxf(m1, mx1);
        float a0 = fexp2(m0 - mn0), a1 = fexp2(m1 - mn1);
        m0 = mn0; m1 = mn1;

        float rs0 = 0.f, rs1 = 0.f;
        unsigned pa[4][4];
        #pragma unroll
        for (int nt = 0; nt < 8; nt++) {
            float p0 = fexp2(s[nt][0] - m0);
            float p1 = fexp2(s[nt][1] - m0);
            float p2 = fexp2(s[nt][2] - m1);
            float p3 = fexp2(s[nt][3] - m1);
            rs0 += p0 + p1; rs1 += p2 + p3;
            pa[nt >> 1][(nt & 1) * 2 + 0] = hpack(p0, p1);
            pa[nt >> 1][(nt & 1) * 2 + 1] = hpack(p2, p3);
        }
        rs0 += __shfl_xor_sync(0xffffffffu, rs0, 1);
        rs0 += __shfl_xor_sync(0xffffffffu, rs0, 2);
        rs1 += __shfl_xor_sync(0xffffffffu, rs1, 1);
        rs1 += __shfl_xor_sync(0xffffffffu, rs1, 2);
        l0 = l0 * a0 + rs0;
        l1 = l1 * a1 + rs1;
        #pragma unroll
        for (int j = 0; j < 8; j++) {
            o[j][0] *= a0; o[j][1] *= a0; o[j][2] *= a1; o[j][3] *= a1;
        }

        #pragma unroll
        for (int ks = 0; ks < 4; ks++) {
            #pragma unroll
            for (int p = 0; p < 4; p++) {
                unsigned r0, r1, r2, r3;
                ldsm4t(r0, r1, r2, r3, sVa[cb] + vfoff + (uint32_t)(ks * 16) * (ATP * 2) + p * 32);
                mma_f16(o[2*p],   pa[ks], r0, r1);
                mma_f16(o[2*p+1], pa[ks], r2, r3);
            }
        }

        if (more) {
            asm volatile("cp.async.wait_group 0;" ::: "memory");
        }
        __syncthreads();   // visibility of next K/V buffer + read-completion
    }

    float i0 = 1.0f / l0, i1 = 1.0f / l1;
    __nv_bfloat16* arow0 = att + (size_t)(b * 1024 + row0) * EDIM + h * 64;
    __nv_bfloat16* arow1 = att + (size_t)(b * 1024 + row1) * EDIM + h * 64;
    #pragma unroll
    for (int nt = 0; nt < 8; nt++) {
        *(unsigned*)&arow0[nt * 8 + c4 * 2] = bfpack(o[nt][0] * i0, o[nt][1] * i0);
        *(unsigned*)&arow1[nt * 8 + c4 * 2] = bfpack(o[nt][2] * i1, o[nt][3] * i1);
    }
}

// ---------------------------------------------------------------------------
extern "C" void kernel_launch(void* const* d_in, const int* in_sizes, int n_in,
                              void* d_out, int out_size)
{
    const float* x    = (const float*)d_in[0];
    const float* ln1w = (const float*)d_in[1];
    const float* ln1b = (const float*)d_in[2];
    const float* ln2w = (const float*)d_in[3];
    const float* ln2b = (const float*)d_in[4];
    const float* qkvw = (const float*)d_in[5];
    const float* qkvb = (const float*)d_in[6];
    const float* outw = (const float*)d_in[7];
    const float* outb = (const float*)d_in[8];
    const float* fc1w = (const float*)d_in[9];
    const float* fc1b = (const float*)d_in[10];
    const float* fc2w = (const float*)d_in[11];
    const float* fc2b = (const float*)d_in[12];
    float* out = (float*)d_out;

    __nv_bfloat16 *h, *att, *ff, *w;
    __half *qkv;
    float *x1;
    cudaGetSymbolAddress((void**)&h,   g_h);
    cudaGetSymbolAddress((void**)&qkv, g_qkv);
    cudaGetSymbolAddress((void**)&att, g_att);
    cudaGetSymbolAddress((void**)&x1,  g_x1);
    cudaGetSymbolAddress((void**)&ff,  g_ff);
    cudaGetSymbolAddress((void**)&w,   g_w);

    __nv_bfloat16* wq = w + OFF_WQKV;
    __nv_bfloat16* wo = w + OFF_WOUT;
    __nv_bfloat16* w1 = w + OFF_WFC1;
    __nv_bfloat16* w2 = w + OFF_WFC2;

    const int SMEM = 3 * (128 + 128) * 144;   // 110592 bytes -> 2 CTAs/SM
    cudaFuncSetAttribute(gemm_tc<1>, cudaFuncAttributeMaxDynamicSharedMemorySize, SMEM);
    cudaFuncSetAttribute(gemm_tc<2>, cudaFuncAttributeMaxDynamicSharedMemorySize, SMEM);
    cudaFuncSetAttribute(gemm_tc<3>, cudaFuncAttributeMaxDynamicSharedMemorySize, SMEM);
    cudaFuncSetAttribute(attn_fa,    cudaFuncAttributeMaxDynamicSharedMemorySize, ATT_SMEM);

    // 0) LN1 -> bf16
    ln_kernel<<<NTOK, 256>>>(x, ln1w, ln1b, h);
    // 1) weights qkv+out -> bf16
    cvt2<<<1024, 256>>>((const float4*)qkvw, (uint2*)wq, 768, (const float4*)outw, (uint2*)wo);
    // 2) weights fc1+fc2 -> bf16
    cvt2<<<2048, 256>>>((const float4*)fc1w, (uint2*)w1, 1024, (const float4*)fc2w, (uint2*)w2);
    // 3) QKV projection -> fp16 qkv   (same ncu slot for A/B compare)
    gemm_tc<3><<<dim3(3*EDIM/128, NTOK/128), 256, SMEM>>>(h, wq, qkvb, nullptr, qkv, NTOK, 3*EDIM, EDIM);
    // 4) FA2 attention -> bf16 att
    attn_fa<<<dim3(8, 4*NH), 256, ATT_SMEM>>>(qkv, att);
    // 5) out projection + residual(x) -> fp32 x1
    gemm_tc<1><<<dim3(EDIM/128, NTOK/128), 256, SMEM>>>(att, wo, outb, x, x1, NTOK, EDIM, EDIM);
    // 6) LN2 -> bf16
    ln_kernel<<<NTOK, 256>>>(x1, ln2w, ln2b, h);
    // 7) FC1 + GELU -> bf16 ff
    gemm_tc<2><<<dim3(FDIM/128, NTOK/128), 256, SMEM>>>(h, w1, fc1b, nullptr, ff, NTOK, FDIM, EDIM);
    // 8) FC2 + residual(x1) -> fp32 out
    gemm_tc<1><<<dim3(EDIM/128, NTOK/128), 256, SMEM>>>(ff, w2, fc2b, x1, out, NTOK, EDIM, FDIM);
}

// round 14
// speedup vs baseline: 1.0246x; 1.0246x over previous
#include <cuda_runtime.h>
#include <cuda_bf16.h>
#include <cuda_fp16.h>
#include <math.h>
#include <stdint.h>

#define EDIM 1024
#define NTOK 4096          // B*T
#define FDIM 4096
#define NH   16

// ---------------- scratch (__device__ globals; no allocs allowed) ----------
__device__ __nv_bfloat16 g_h  [NTOK * EDIM];            // LN out (bf16)
__device__ __half        g_qkv[NTOK * 3 * EDIM];        // fp16 (attn input)
__device__ __nv_bfloat16 g_att[NTOK * EDIM];            // attn out (bf16)
__device__ float         g_x1 [NTOK * EDIM];            // residual after attn
__device__ __nv_bfloat16 g_ff [(size_t)NTOK * FDIM];    // fc1-gelu out (bf16)
__device__ __nv_bfloat16 g_w  [12 * 1024 * 1024];       // bf16 weights
#define OFF_WQKV 0
#define OFF_WOUT (3*1024*1024)
#define OFF_WFC1 (4*1024*1024)
#define OFF_WFC2 (8*1024*1024)

__device__ __forceinline__ unsigned bfpack(float lo, float hi) {
    __nv_bfloat162 p = __floats2bfloat162_rn(lo, hi);
    return *(unsigned*)&p;
}
__device__ __forceinline__ unsigned hpack(float lo, float hi) {
    __half2 p = __floats2half2_rn(lo, hi);
    return *(unsigned*)&p;
}

// fast 2^y for softmax (y<=0): exponent bits + deg-5 poly on frac. FMA-pipe only.
__device__ __forceinline__ float fexp2(float y) {
    y = fmaxf(y, -80.f);
    float fl = floorf(y);
    float f = y - fl;
    float p =            1.3333558146e-3f;
    p = fmaf(p, f, 9.6181291076e-3f);
    p = fmaf(p, f, 5.5504108664e-2f);
    p = fmaf(p, f, 2.4022650696e-1f);
    p = fmaf(p, f, 6.9314718056e-1f);
    p = fmaf(p, f, 1.0f);
    int e = (int)fl;
    return p * __int_as_float((e + 127) << 23);
}

__device__ __forceinline__ void mma_bf16(float* d, const unsigned* a, const unsigned* b) {
    asm volatile(
        "mma.sync.aligned.m16n8k16.row.col.f32.bf16.bf16.f32 "
        "{%0,%1,%2,%3},{%4,%5,%6,%7},{%8,%9},{%0,%1,%2,%3};"
        : "+f"(d[0]), "+f"(d[1]), "+f"(d[2]), "+f"(d[3])
        : "r"(a[0]), "r"(a[1]), "r"(a[2]), "r"(a[3]), "r"(b[0]), "r"(b[1]));
}
__device__ __forceinline__ void mma_f16(float* d, const unsigned* a, unsigned b0, unsigned b1) {
    asm volatile(
        "mma.sync.aligned.m16n8k16.row.col.f32.f16.f16.f32 "
        "{%0,%1,%2,%3},{%4,%5,%6,%7},{%8,%9},{%0,%1,%2,%3};"
        : "+f"(d[0]), "+f"(d[1]), "+f"(d[2]), "+f"(d[3])
        : "r"(a[0]), "r"(a[1]), "r"(a[2]), "r"(a[3]), "r"(b0), "r"(b1));
}
__device__ __forceinline__ void ldsm4(unsigned& r0, unsigned& r1, unsigned& r2, unsigned& r3, uint32_t addr) {
    asm volatile("ldmatrix.sync.aligned.m8n8.x4.shared.b16 {%0,%1,%2,%3}, [%4];"
                 : "=r"(r0), "=r"(r1), "=r"(r2), "=r"(r3) : "r"(addr));
}
__device__ __forceinline__ void ldsm4t(unsigned& r0, unsigned& r1, unsigned& r2, unsigned& r3, uint32_t addr) {
    asm volatile("ldmatrix.sync.aligned.m8n8.x4.trans.shared.b16 {%0,%1,%2,%3}, [%4];"
                 : "=r"(r0), "=r"(r1), "=r"(r2), "=r"(r3) : "r"(addr));
}

__device__ __forceinline__ uint32_t smem_u32g(const void* p) {
    uint32_t a;
    asm("{ .reg .u64 t; cvta.to.shared.u64 t, %1; cvt.u32.u64 %0, t; }" : "=r"(a) : "l"(p));
    return a;
}

// ---------------- weight convert: two tensors per launch --------------------
__global__ __launch_bounds__(256) void cvt2(
    const float4* __restrict__ sA, uint2* __restrict__ dA, int nA,
    const float4* __restrict__ sB, uint2* __restrict__ dB)
{
    int bid = blockIdx.x;
    const float4* s; uint2* d; int local;
    if (bid < nA) { s = sA; d = dA; local = bid; }
    else          { s = sB; d = dB; local = bid - nA; }
    int i0 = local * 1024 + threadIdx.x;
    float4 v0 = s[i0];
    float4 v1 = s[i0 + 256];
    float4 v2 = s[i0 + 512];
    float4 v3 = s[i0 + 768];
    d[i0]       = (uint2){ bfpack(v0.x, v0.y), bfpack(v0.z, v0.w) };
    d[i0 + 256] = (uint2){ bfpack(v1.x, v1.y), bfpack(v1.z, v1.w) };
    d[i0 + 512] = (uint2){ bfpack(v2.x, v2.y), bfpack(v2.z, v2.w) };
    d[i0 + 768] = (uint2){ bfpack(v3.x, v3.y), bfpack(v3.z, v3.w) };
}

// ---------------- LayerNorm (fp32 in, bf16 out) ----------------------------
__global__ __launch_bounds__(256) void ln_kernel(
    const float* __restrict__ x, const float* __restrict__ w,
    const float* __restrict__ b, __nv_bfloat16* __restrict__ out)
{
    __shared__ float red[2][8];
    int row = blockIdx.x;
    int tid = threadIdx.x;
    const float4* xr = (const float4*)(x + (size_t)row * EDIM);
    float4 v = xr[tid];
    float s  = v.x + v.y + v.z + v.w;
    float ss = v.x*v.x + v.y*v.y + v.z*v.z + v.w*v.w;
    #pragma unroll
    for (int o = 16; o; o >>= 1) {
        s  += __shfl_xor_sync(0xffffffffu, s,  o);
        ss += __shfl_xor_sync(0xffffffffu, ss, o);
    }
    int wid = tid >> 5, lid = tid & 31;
    if (lid == 0) { red[0][wid] = s; red[1][wid] = ss; }
    __syncthreads();
    s = 0.f; ss = 0.f;
    #pragma unroll
    for (int i = 0; i < 8; i++) { s += red[0][i]; ss += red[1][i]; }
    float mu  = s * (1.0f / EDIM);
    float var = ss * (1.0f / EDIM) - mu * mu;
    float inv = rsqrtf(var + 1e-5f);
    float4 wv = ((const float4*)w)[tid];
    float4 bv = ((const float4*)b)[tid];
    float o0 = (v.x - mu) * inv * wv.x + bv.x;
    float o1 = (v.y - mu) * inv * wv.y + bv.y;
    float o2 = (v.z - mu) * inv * wv.z + bv.z;
    float o3 = (v.w - mu) * inv * wv.w + bv.w;
    uint2 o = { bfpack(o0, o1), bfpack(o2, o3) };
    ((uint2*)(out + (size_t)row * EDIM))[tid] = o;
}

// ---------------------------------------------------------------------------
// bf16 mma.sync GEMM, 2 CTAs/SM, 128 threads (4 warps), 64x64 warp tiles.
// C[M,N] = A[M,K] @ Bw[N,K]^T. Tile 128x128xBK64, warp grid 2(m)x2(n).
// Bigger warp tiles: fragment LDSM traffic 96->64 KB per CTA-tile.
// 3-stage cp.async, R11-proven order: wait(t) -> sync -> prefetch(t+2) -> mma.
// Rows 128B data + 16B pad (stride 144B) -> conflict-free ldmatrix.
// EPI: 0 = +bias -> fp32; 1 = +bias+residual -> fp32;
//      2 = +bias+GELU -> bf16; 3 = +bias -> fp16
// ---------------------------------------------------------------------------
template <int EPI>
__global__ __launch_bounds__(128, 2) void gemm_tc(
    const __nv_bfloat16* __restrict__ A, const __nv_bfloat16* __restrict__ Bw,
    const float* __restrict__ bias, const float* __restrict__ R,
    void* __restrict__ Cv, int M, int N, int K)
{
    constexpr int BM = 128, BN = 128, NST = 3;
    constexpr uint32_t ROWB  = 144;
    constexpr uint32_t AOFF  = BM * ROWB;              // 18432
    constexpr uint32_t STAGE = (BM + BN) * ROWB;       // 36864 B

    extern __shared__ char dsm[];
    uint32_t sb = smem_u32g(dsm);
    int tid = threadIdx.x, warp = tid >> 5, lane = tid & 31;
    int m0 = blockIdx.y * BM, n0 = blockIdx.x * BN;
    int wm = (warp >> 1) * 64;         // 0 / 64
    int wn = (warp & 1) * 64;          // 0 / 64
    int T = K >> 6;

    float acc[4][8][4];
    #pragma unroll
    for (int i = 0; i < 4; i++)
        #pragma unroll
        for (int j = 0; j < 8; j++)
            #pragma unroll
            for (int k = 0; k < 4; k++) acc[i][j][k] = 0.f;

    auto load_tile = [&](int t, int s) {
        int k0 = t << 6;
        uint32_t base = sb + (uint32_t)s * STAGE;
        #pragma unroll
        for (int j = 0; j < 16; j++) {
            int idx = tid + j * 128;            // 2048 16B-chunks per stage
            bool isB = idx >= 1024;
            int li = idx & 1023;
            int r  = li >> 3;
            int ch = li & 7;
            const __nv_bfloat16* g = isB ? (Bw + (size_t)(n0 + r) * K + k0 + ch * 8)
                                         : (A  + (size_t)(m0 + r) * K + k0 + ch * 8);
            uint32_t dst = base + (isB ? AOFF : 0u) + (uint32_t)r * ROWB + ch * 16;
            asm volatile("cp.async.cg.shared.global [%0], [%1], 16;" :: "r"(dst), "l"(g));
        }
    };

    load_tile(0, 0);
    asm volatile("cp.async.commit_group;" ::: "memory");
    load_tile(1, 1);
    asm volatile("cp.async.commit_group;" ::: "memory");

    uint32_t lm   = lane & 15;
    uint32_t hi16 = ((lane >> 4) & 1) * 16;
    uint32_t aoff[4], boff[4];
    #pragma unroll
    for (int mt = 0; mt < 4; mt++) aoff[mt] = (uint32_t)(wm + mt * 16 + lm) * ROWB + hi16;
    #pragma unroll
    for (int p = 0; p < 4; p++)    boff[p]  = AOFF + (uint32_t)(wn + p * 16 + lm) * ROWB + hi16;

    for (int t = 0; t < T; t++) {
        asm volatile("cp.async.wait_group 1;" ::: "memory");
        __syncthreads();

        if (t + 2 < T) load_tile(t + 2, (t + 2) % NST);
        asm volatile("cp.async.commit_group;" ::: "memory");

        uint32_t base = sb + (uint32_t)(t % NST) * STAGE;

        #pragma unroll
        for (int ks = 0; ks < 4; ks++) {
            unsigned a[4][4], b[8][2];
            #pragma unroll
            for (int mt = 0; mt < 4; mt++)
                ldsm4(a[mt][0], a[mt][1], a[mt][2], a[mt][3], base + aoff[mt] + ks * 32);
            #pragma unroll
            for (int p = 0; p < 4; p++) {
                unsigned r0, r1, r2, r3;
                ldsm4(r0, r1, r2, r3, base + boff[p] + ks * 32);
                b[2*p][0] = r0; b[2*p+1][0] = r1; b[2*p][1] = r2; b[2*p+1][1] = r3;
            }
            #pragma unroll
            for (int mt = 0; mt < 4; mt++)
                #pragma unroll
                for (int nt = 0; nt < 8; nt++)
                    mma_bf16(acc[mt][nt], a[mt], b[nt]);
        }
    }

    // epilogue
    float* C = (float*)Cv;
    __nv_bfloat16* Cb = (__nv_bfloat16*)Cv;
    __half* Ch = (__half*)Cv;
    int q = lane >> 2;
    int cc = (lane & 3) * 2;
    #pragma unroll
    for (int mt = 0; mt < 4; mt++) {
        #pragma unroll
        for (int nt = 0; nt < 8; nt++) {
            int row = m0 + wm + mt * 16 + q;
            int col = n0 + wn + nt * 8 + cc;
            float bx = bias[col], by = bias[col + 1];
            float v0 = acc[mt][nt][0] + bx, v1 = acc[mt][nt][1] + by;
            float v2 = acc[mt][nt][2] + bx, v3 = acc[mt][nt][3] + by;
            if (EPI == 1) {
                float2 r0 = *(const float2*)&R[(size_t)row * N + col];
                float2 r1 = *(const float2*)&R[(size_t)(row + 8) * N + col];
                v0 += r0.x; v1 += r0.y; v2 += r1.x; v3 += r1.y;
            }
            if (EPI == 2) {
                v0 = 0.5f * v0 * (1.0f + erff(v0 * 0.70710678118f));
                v1 = 0.5f * v1 * (1.0f + erff(v1 * 0.70710678118f));
                v2 = 0.5f * v2 * (1.0f + erff(v2 * 0.70710678118f));
                v3 = 0.5f * v3 * (1.0f + erff(v3 * 0.70710678118f));
                *(unsigned*)&Cb[(size_t)row * N + col]       = bfpack(v0, v1);
                *(unsigned*)&Cb[(size_t)(row + 8) * N + col] = bfpack(v2, v3);
            } else if (EPI == 3) {
                *(unsigned*)&Ch[(size_t)row * N + col]       = hpack(v0, v1);
                *(unsigned*)&Ch[(size_t)(row + 8) * N + col] = hpack(v2, v3);
            } else {
                float2 o0 = {v0, v1}, o1 = {v2, v3};
                *(float2*)&C[(size_t)row * N + col] = o0;
                *(float2*)&C[(size_t)(row + 8) * N + col] = o1;
            }
        }
    }
}

// ---------------------------------------------------------------------------
// FA2 causal attention (R13, passing): 128-query CTA, 256 threads.
// fp16 mma; K/V cp.async double-buffered [s][d]; V frags via ldmatrix.trans.
// Softmax in exp2 domain: Q pre-scaled by (1/8)*log2e.
// ---------------------------------------------------------------------------
#define ATP 72
#define ATT_SMEM 55296
__global__ __launch_bounds__(256, 2) void attn_fa(
    const __half* __restrict__ qkv, __nv_bfloat16* __restrict__ att)
{
    extern __shared__ char asmem[];
    uint32_t sb = smem_u32g(asmem);
    uint32_t sQ = sb;
    uint32_t sKa[2] = { sb + 18432, sb + 27648 };
    uint32_t sVa[2] = { sb + 36864, sb + 46080 };

    int qt = 7 - blockIdx.x;
    int bh = blockIdx.y;
    int b = bh >> 4, h = bh & 15;
    int tid = threadIdx.x, warp = tid >> 5, lane = tid & 31;
    int g = lane >> 2, c4 = lane & 3;
    uint32_t lm = lane & 15;
    uint32_t hi16 = ((lane >> 4) & 1) * 16;

    const __half* base = qkv + (size_t)b * 1024 * 3072 + h * 64;

    auto loadQ = [&]() {
        #pragma unroll
        for (int i = 0; i < 4; i++) {
            int idx = tid + i * 256;
            int r = idx >> 3, ch = idx & 7;
            const __half* gp = base + (size_t)(qt * 128 + r) * 3072 + ch * 8;
            asm volatile("cp.async.cg.shared.global [%0], [%1], 16;"
                         :: "r"(sQ + r * (ATP * 2) + ch * 16), "l"(gp));
        }
    };
    auto loadKV = [&](int kt, int buf) {
        #pragma unroll
        for (int i = 0; i < 4; i++) {
            int idx = tid + i * 256;
            bool isV = idx >= 512;
            int li = isV ? idx - 512 : idx;
            int r = li >> 3, ch = li & 7;
            const __half* gp = base + (size_t)(kt * 64 + r) * 3072
                             + (isV ? 2048 : 1024) + ch * 8;
            uint32_t dst = (isV ? sVa[buf] : sKa[buf]) + r * (ATP * 2) + ch * 16;
            asm volatile("cp.async.cg.shared.global [%0], [%1], 16;"
                         :: "r"(dst), "l"(gp));
        }
    };

    loadQ();
    loadKV(0, 0);
    asm volatile("cp.async.commit_group;" ::: "memory");
    asm volatile("cp.async.wait_group 0;" ::: "memory");
    __syncthreads();

    unsigned qa[4][4];
    {
        uint32_t qoff = sQ + (uint32_t)(warp * 16 + lm) * (ATP * 2) + hi16;
        #pragma unroll
        for (int s = 0; s < 4; s++)
            ldsm4(qa[s][0], qa[s][1], qa[s][2], qa[s][3], qoff + s * 32);
        __half2 sc = __float2half2_rn(0.18033688f);   // 0.125 * log2(e)
        #pragma unroll
        for (int s = 0; s < 4; s++)
            #pragma unroll
            for (int j = 0; j < 4; j++) {
                __half2 v = __hmul2(*(__half2*)&qa[s][j], sc);
                qa[s][j] = *(unsigned*)&v;
            }
    }

    int vm = lane >> 3, vr8 = lane & 7;
    uint32_t vfoff = (uint32_t)(((vm & 1) * 8 + vr8) * (ATP * 2) + (vm >> 1) * 16);

    float m0 = -1e30f, m1 = -1e30f, l0 = 0.f, l1 = 0.f;
    float o[8][4];
    #pragma unroll
    for (int j = 0; j < 8; j++)
        #pragma unroll
        for (int e = 0; e < 4; e++) o[j][e] = 0.f;

    int row0 = qt * 128 + warp * 16 + g, row1 = row0 + 8;
    int nkt = 2 * qt + 2;

    for (int kt = 0; kt < nkt; kt++) {
        int cb = kt & 1;
        bool more = kt + 1 < nkt;
        if (more) {
            loadKV(kt + 1, cb ^ 1);
            asm volatile("cp.async.commit_group;" ::: "memory");
        }

        float s[8][4];
        #pragma unroll
        for (int j = 0; j < 8; j++)
            #pragma unroll
            for (int e = 0; e < 4; e++) s[j][e] = 0.f;
        #pragma unroll
        for (int ks = 0; ks < 4; ks++) {
            #pragma unroll
            for (int p = 0; p < 4; p++) {
                unsigned r0, r1, r2, r3;
                ldsm4(r0, r1, r2, r3, sKa[cb] + (uint32_t)(p * 16 + lm) * (ATP * 2) + hi16 + ks * 32);
                mma_f16(s[2*p],   qa[ks], r0, r2);
                mma_f16(s[2*p+1], qa[ks], r1, r3);
            }
        }

        if (kt >= 2 * qt) {
            int colb = kt * 64 + c4 * 2;
            #pragma unroll
            for (int nt = 0; nt < 8; nt++) {
                int c0 = colb + nt * 8, c1 = c0 + 1;
                s[nt][0] = (c0 <= row0) ? s[nt][0] : -1e30f;
                s[nt][1] = (c1 <= row0) ? s[nt][1] : -1e30f;
                s[nt][2] = (c0 <= row1) ? s[nt][2] : -1e30f;
                s[nt][3] = (c1 <= row1) ? s[nt][3] : -1e30f;
            }
        }

        float mx0 = -1e30f, mx1 = -1e30f;
        #pragma unroll
        for (int nt = 0; nt < 8; nt++) {
            mx0 = fmaxf(mx0, fmaxf(s[nt][0], s[nt][1]));
            mx1 = fmaxf(mx1, fmaxf(s[nt][2], s[nt][3]));
        }
        mx0 = fmaxf(mx0, __shfl_xor_sync(0xffffffffu, mx0, 1));
        mx0 = fmaxf(mx0, __shfl_xor_sync(0xffffffffu, mx0, 2));
        mx1 = fmaxf(mx1, __shfl_xor_sync(0xffffffffu, mx1, 1));
        mx1 = fmaxf(mx1, __shfl_xor_sync(0xffffffffu, mx1, 2));
        float mn0 = fmaxf(m0, mx0), mn1 = fmaxf(m1, mx1);
        float a0 = fexp2(m0 - mn0), a1 = fexp2(m1 - mn1);
        m0 = mn0; m1 = mn1;

        float rs0 = 0.f, rs1 = 0.f;
        unsigned pa[4][4];
        #pragma unroll
        for (int nt = 0; nt < 8; nt++) {
            float p0 = fexp2(s[nt][0] - m0);
            float p1 = fexp2(s[nt][1] - m0);
            float p2 = fexp2(s[nt][2] - m1);
            float p3 = fexp2(s[nt][3] - m1);
            rs0 += p0 + p1; rs1 += p2 + p3;
            pa[nt >> 1][(nt & 1) * 2 + 0] = hpack(p0, p1);
            pa[nt >> 1][(nt & 1) * 2 + 1] = hpack(p2, p3);
        }
        rs0 += __shfl_xor_sync(0xffffffffu, rs0, 1);
        rs0 += __shfl_xor_sync(0xffffffffu, rs0, 2);
        rs1 += __shfl_xor_sync(0xffffffffu, rs1, 1);
        rs1 += __shfl_xor_sync(0xffffffffu, rs1, 2);
        l0 = l0 * a0 + rs0;
        l1 = l1 * a1 + rs1;
        #pragma unroll
        for (int j = 0; j < 8; j++) {
            o[j][0] *= a0; o[j][1] *= a0; o[j][2] *= a1; o[j][3] *= a1;
        }

        #pragma unroll
        for (int ks = 0; ks < 4; ks++) {
            #pragma unroll
            for (int p = 0; p < 4; p++) {
                unsigned r0, r1, r2, r3;
                ldsm4t(r0, r1, r2, r3, sVa[cb] + vfoff + (uint32_t)(ks * 16) * (ATP * 2) + p * 32);
                mma_f16(o[2*p],   pa[ks], r0, r1);
                mma_f16(o[2*p+1], pa[ks], r2, r3);
            }
        }

        if (more) {
            asm volatile("cp.async.wait_group 0;" ::: "memory");
        }
        __syncthreads();
    }

    float i0 = 1.0f / l0, i1 = 1.0f / l1;
    __nv_bfloat16* arow0 = att + (size_t)(b * 1024 + row0) * EDIM + h * 64;
    __nv_bfloat16* arow1 = att + (size_t)(b * 1024 + row1) * EDIM + h * 64;
    #pragma unroll
    for (int nt = 0; nt < 8; nt++) {
        *(unsigned*)&arow0[nt * 8 + c4 * 2] = bfpack(o[nt][0] * i0, o[nt][1] * i0);
        *(unsigned*)&arow1[nt * 8 + c4 * 2] = bfpack(o[nt][2] * i1, o[nt][3] * i1);
    }
}

// ---------------------------------------------------------------------------
extern "C" void kernel_launch(void* const* d_in, const int* in_sizes, int n_in,
                              void* d_out, int out_size)
{
    const float* x    = (const float*)d_in[0];
    const float* ln1w = (const float*)d_in[1];
    const float* ln1b = (const float*)d_in[2];
    const float* ln2w = (const float*)d_in[3];
    const float* ln2b = (const float*)d_in[4];
    const float* qkvw = (const float*)d_in[5];
    const float* qkvb = (const float*)d_in[6];
    const float* outw = (const float*)d_in[7];
    const float* outb = (const float*)d_in[8];
    const float* fc1w = (const float*)d_in[9];
    const float* fc1b = (const float*)d_in[10];
    const float* fc2w = (const float*)d_in[11];
    const float* fc2b = (const float*)d_in[12];
    float* out = (float*)d_out;

    __nv_bfloat16 *h, *att, *ff, *w;
    __half *qkv;
    float *x1;
    cudaGetSymbolAddress((void**)&h,   g_h);
    cudaGetSymbolAddress((void**)&qkv, g_qkv);
    cudaGetSymbolAddress((void**)&att, g_att);
    cudaGetSymbolAddress((void**)&x1,  g_x1);
    cudaGetSymbolAddress((void**)&ff,  g_ff);
    cudaGetSymbolAddress((void**)&w,   g_w);

    __nv_bfloat16* wq = w + OFF_WQKV;
    __nv_bfloat16* wo = w + OFF_WOUT;
    __nv_bfloat16* w1 = w + OFF_WFC1;
    __nv_bfloat16* w2 = w + OFF_WFC2;

    const int SMEM = 3 * (128 + 128) * 144;   // 110592 bytes -> 2 CTAs/SM
    cudaFuncSetAttribute(gemm_tc<1>, cudaFuncAttributeMaxDynamicSharedMemorySize, SMEM);
    cudaFuncSetAttribute(gemm_tc<2>, cudaFuncAttributeMaxDynamicSharedMemorySize, SMEM);
    cudaFuncSetAttribute(gemm_tc<3>, cudaFuncAttributeMaxDynamicSharedMemorySize, SMEM);
    cudaFuncSetAttribute(attn_fa,    cudaFuncAttributeMaxDynamicSharedMemorySize, ATT_SMEM);

    // 0) LN1 -> bf16
    ln_kernel<<<NTOK, 256>>>(x, ln1w, ln1b, h);
    // 1) weights qkv+out -> bf16
    cvt2<<<1024, 256>>>((const float4*)qkvw, (uint2*)wq, 768, (const float4*)outw, (uint2*)wo);
    // 2) weights fc1+fc2 -> bf16
    cvt2<<<2048, 256>>>((const float4*)fc1w, (uint2*)w1, 1024, (const float4*)fc2w, (uint2*)w2);
    // 3) QKV projection -> fp16 qkv   (same ncu slot for A/B compare)
    gemm_tc<3><<<dim3(3*EDIM/128, NTOK/128), 128, SMEM>>>(h, wq, qkvb, nullptr, qkv, NTOK, 3*EDIM, EDIM);
    // 4) FA2 attention -> bf16 att
    attn_fa<<<dim3(8, 4*NH), 256, ATT_SMEM>>>(qkv, att);
    // 5) out projection + residual(x) -> fp32 x1
    gemm_tc<1><<<dim3(EDIM/128, NTOK/128), 128, SMEM>>>(att, wo, outb, x, x1, NTOK, EDIM, EDIM);
    // 6) LN2 -> bf16
    ln_kernel<<<NTOK, 256>>>(x1, ln2w, ln2b, h);
    // 7) FC1 + GELU -> bf16 ff
    gemm_tc<2><<<dim3(FDIM/128, NTOK/128), 128, SMEM>>>(h, w1, fc1b, nullptr, ff, NTOK, FDIM, EDIM);
    // 8) FC2 + residual(x1) -> fp32 out
    gemm_tc<1><<<dim3(EDIM/128, NTOK/128), 128, SMEM>>>(ff, w2, fc2b, x1, out, NTOK, EDIM, FDIM);
}